// round 12
// baseline (speedup 1.0000x reference)
#include <cuda_runtime.h>
#include <cstdint>

#define E_DIM 128
#define B_SZ  1024
#define T_SZ  200
#define NTHR  256

#define ROW_A 272            // 128 fp16 padded to 272B (ldmatrix conflict-free)
#define ROW_W 132

#define OFF_A    0           // 208*272 = 56576
#define OFF_STG  56576       // 2 x 25600 fp32 staging (50 rows each)
#define STG_SZ   25600
#define OFF_RED  107776      // 2*208 f32 = 1664
#define SMEM_BYTES 109440    // x2 CTAs = 218880 <= 228KB

// Precomputed per-batch B in mma-fragment layout: [b][ng(2)][nt(4)][k2(4)][lane(32)] uint4
__device__ uint4 g_Wbf[B_SZ * 1024];
__device__ float g_qA[B_SZ * 64];       // b0 folded in

__device__ __forceinline__ uint32_t pkf16(float lo, float hi) {
    uint32_t r;
    asm("cvt.rn.f16x2.f32 %0, %1, %2;" : "=r"(r) : "f"(hi), "f"(lo));
    return r;
}
__device__ __forceinline__ uint32_t smem_u32(const void* p) {
    uint32_t a;
    asm("{ .reg .u64 t; cvta.to.shared.u64 t, %1; cvt.u32.u64 %0, t; }" : "=r"(a) : "l"(p));
    return a;
}
__device__ __forceinline__ void cp16(uint32_t dst, const float4* src) {
    asm volatile("cp.async.cg.shared.global [%0], [%1], 16;"
                 :: "r"(dst), "l"(__cvta_generic_to_global(src)) : "memory");
}
#define CP_COMMIT() asm volatile("cp.async.commit_group;" ::: "memory")
#define CP_WAIT(n)  asm volatile("cp.async.wait_group %0;" :: "n"(n) : "memory")

#define LDSM4(r, addr) \
    asm volatile("ldmatrix.sync.aligned.m8n8.x4.shared.b16 {%0,%1,%2,%3}, [%4];" \
        : "=r"((r)[0]), "=r"((r)[1]), "=r"((r)[2]), "=r"((r)[3]) : "r"(addr))

__device__ __forceinline__ void mma_f16(float* c, const uint32_t* a, uint32_t b0, uint32_t b1) {
    asm volatile("mma.sync.aligned.m16n8k16.row.col.f32.f16.f16.f32 "
        "{%0,%1,%2,%3}, {%4,%5,%6,%7}, {%8,%9}, {%0,%1,%2,%3};"
        : "+f"(c[0]), "+f"(c[1]), "+f"(c[2]), "+f"(c[3])
        : "r"(a[0]), "r"(a[1]), "r"(a[2]), "r"(a[3]), "r"(b0), "r"(b1));
}

// ---- prep: fold W0 once; emit W_b fragments + qA for all batches ----
// grid 64, block 256; block i handles batches 16i..16i+15
__global__ void __launch_bounds__(256, 1) prep(
    const float* __restrict__ W0, const float* __restrict__ query,
    const float* __restrict__ b0)
{
    extern __shared__ float ps[];
    float* sWk = ps;                        // 64*132
    float* sWd = ps + 64 * ROW_W;
    float* sWq = ps + 2 * 64 * ROW_W;
    float* sq  = ps + 3 * 64 * ROW_W;       // 128
    float* sr  = sq + 128;                  // 256
    const int tid = threadIdx.x;

    for (int idx = tid; idx < 8192; idx += 256) {
        int h = idx & 63, e = idx >> 6;
        float wa = W0[e * 64 + h];
        float wb = W0[(128 + e) * 64 + h];
        float wc = W0[(256 + e) * 64 + h];
        float wd = W0[(384 + e) * 64 + h];
        sWk[h * ROW_W + e] = wb - wc;
        sWd[h * ROW_W + e] = wd;
        sWq[h * ROW_W + e] = wa + wc;
    }
    __syncthreads();

    for (int bi = 0; bi < 16; bi++) {
        const int b = blockIdx.x * 16 + bi;
        if (tid < 128) sq[tid] = query[(size_t)b * E_DIM + tid];
        __syncthreads();

        // W_b fragments: 1024 uint4 per batch, mapping mirrors ldmatrix output
        #pragma unroll
        for (int j = 0; j < 4; j++) {
            int id = j * 256 + tid;
            int lane = id & 31, k2 = (id >> 5) & 3, nt = (id >> 7) & 3, ng = id >> 9;
            int n = lane >> 2, kc = 2 * (lane & 3);
            int h = ng * 32 + nt * 8 + n;
            int e0 = 32 * k2 + kc, e1 = e0 + 16;
            const float* wk = sWk + h * ROW_W;
            const float* wd = sWd + h * ROW_W;
            uint4 v;
            v.x = pkf16(fmaf(sq[e0],     wd[e0],     wk[e0]),
                        fmaf(sq[e0 + 1], wd[e0 + 1], wk[e0 + 1]));
            v.y = pkf16(fmaf(sq[e0 + 8], wd[e0 + 8], wk[e0 + 8]),
                        fmaf(sq[e0 + 9], wd[e0 + 9], wk[e0 + 9]));
            v.z = pkf16(fmaf(sq[e1],     wd[e1],     wk[e1]),
                        fmaf(sq[e1 + 1], wd[e1 + 1], wk[e1 + 1]));
            v.w = pkf16(fmaf(sq[e1 + 8], wd[e1 + 8], wk[e1 + 8]),
                        fmaf(sq[e1 + 9], wd[e1 + 9], wk[e1 + 9]));
            g_Wbf[(size_t)b * 1024 + id] = v;
        }

        // qA[b][h] = b0[h] + sum_e q[e]*Wq[e,h]
        {
            int h = tid & 63, grp = tid >> 6;
            float p = 0.f;
            #pragma unroll 8
            for (int i = 0; i < 32; i++) {
                int e = grp * 32 + i;
                p += sq[e] * sWq[h * ROW_W + e];
            }
            sr[grp * 64 + h] = p;
        }
        __syncthreads();
        if (tid < 64)
            g_qA[(size_t)b * 64 + tid] = b0[tid] + sr[tid] + sr[64 + tid]
                                       + sr[128 + tid] + sr[192 + tid];
        __syncthreads();
    }
}

// ---- main: one batch per CTA, 2 CTAs/SM ----
__global__ void __launch_bounds__(NTHR, 2) lau_main(
    const float* __restrict__ keys, const float* __restrict__ W1,
    const float* __restrict__ b1,   float* __restrict__ out)
{
    extern __shared__ __align__(1024) char sm[];
    const uint32_t smb = smem_u32(sm);
    const int tid = threadIdx.x;
    const int b = blockIdx.x;
    const int w = tid >> 5, lane = tid & 31;
    const int mg = w >> 1, ng = w & 1;          // 4 m-groups x 2 n-groups
    const int lq = lane >> 2, lr = lane & 3;
    float* sRed = (float*)(sm + OFF_RED);

    const float4* k4 = (const float4*)(keys + (size_t)b * T_SZ * E_DIM);

    // kick both key chunks (50 rows = 1600 float4 each)
    #pragma unroll
    for (int c = 0; c < 2; c++) {
        const float4* src = k4 + c * 1600;
        uint32_t stg = smb + OFF_STG + c * STG_SZ;
        #pragma unroll
        for (int i = 0; i < 7; i++) {
            int idx = i * NTHR + tid;
            if (idx < 1600) cp16(stg + idx * 16, src + idx);
        }
        CP_COMMIT();
    }

    // zero A tail rows 200-207
    if (tid < 136)
        *(uint4*)(sm + OFF_A + 200 * ROW_A + tid * 16) = make_uint4(0, 0, 0, 0);

    // B fragments from gmem (fills cp.async DRAM wait)
    uint32_t bf[4][8][2];
    {
        const uint4* wb4 = g_Wbf + ((size_t)b * 2 + ng) * 512 + lane;
        #pragma unroll
        for (int nt = 0; nt < 4; nt++)
            #pragma unroll
            for (int k2 = 0; k2 < 4; k2++) {
                uint4 v = __ldg(&wb4[nt * 128 + k2 * 32]);
                bf[nt][2 * k2][0] = v.x;     bf[nt][2 * k2][1] = v.y;
                bf[nt][2 * k2 + 1][0] = v.z; bf[nt][2 * k2 + 1][1] = v.w;
            }
    }

    // per-thread epilogue constants
    float qa[8], w1v[8];
    #pragma unroll
    for (int nt = 0; nt < 4; nt++) {
        #pragma unroll
        for (int u = 0; u < 2; u++) {
            int c = ng * 32 + nt * 8 + 2 * lr + u;
            qa[2 * nt + u]  = __ldg(&g_qA[(size_t)b * 64 + c]);
            w1v[2 * nt + u] = __ldg(&W1[c]);
        }
    }
    const float b1v = __ldg(b1);

    // 4 convert phases; each thread converts EXACTLY the addresses it cp.async'd,
    // so wait_group alone provides ordering (no barriers in this loop).
    #pragma unroll
    for (int c = 0; c < 4; c++) {
        CP_WAIT(1);
        const float4* s4 = (const float4*)(sm + OFF_STG + (c & 1) * STG_SZ);
        float4 v[7];
        #pragma unroll
        for (int i = 0; i < 7; i++) {
            int idx = i * NTHR + tid;
            if (idx < 1600) v[i] = s4[idx];
        }
        if (c + 2 < 4) {                         // refill same buffer with next chunk
            const float4* src = k4 + (c + 2) * 1600;
            uint32_t stg = smb + OFF_STG + (c & 1) * STG_SZ;
            #pragma unroll
            for (int i = 0; i < 7; i++) {
                int idx = i * NTHR + tid;
                if (idx < 1600) cp16(stg + idx * 16, src + idx);
            }
        }
        CP_COMMIT();                             // uniform group count across threads
        #pragma unroll
        for (int i = 0; i < 7; i++) {
            int idx = i * NTHR + tid;
            if (idx < 1600) {
                int row = c * 50 + (idx >> 5), cc = idx & 31;
                *(uint2*)(sm + OFF_A + row * ROW_A + cc * 8) =
                    make_uint2(pkf16(v[i].x, v[i].y), pkf16(v[i].z, v[i].w));
            }
        }
    }
    __syncthreads();                             // (1) A complete

    // per-tile mma + inline epilogue
    const uint32_t aB = smb + OFF_A + (lane & 15) * ROW_A + (lane >> 4) * 16;
    #pragma unroll
    for (int i = 0; i < 4; i++) {
        int t = mg + 4 * i;
        if (t < 13) {
            float acc[4][4];
            #pragma unroll
            for (int nt = 0; nt < 4; nt++)
                #pragma unroll
                for (int u = 0; u < 4; u++) acc[nt][u] = 0.f;
            #pragma unroll
            for (int ks = 0; ks < 8; ks++) {
                uint32_t a[4];
                LDSM4(a, aB + t * (16 * ROW_A) + ks * 32);
                #pragma unroll
                for (int nt = 0; nt < 4; nt++)
                    mma_f16(acc[nt], a, bf[nt][ks][0], bf[nt][ks][1]);
            }
            float p0 = 0.f, p1 = 0.f;
            #pragma unroll
            for (int nt = 0; nt < 4; nt++) {
                p0 += fmaxf(acc[nt][0] + qa[2 * nt],     0.f) * w1v[2 * nt]
                    + fmaxf(acc[nt][1] + qa[2 * nt + 1], 0.f) * w1v[2 * nt + 1];
                p1 += fmaxf(acc[nt][2] + qa[2 * nt],     0.f) * w1v[2 * nt]
                    + fmaxf(acc[nt][3] + qa[2 * nt + 1], 0.f) * w1v[2 * nt + 1];
            }
            p0 += __shfl_xor_sync(0xffffffffu, p0, 1);
            p0 += __shfl_xor_sync(0xffffffffu, p0, 2);
            p1 += __shfl_xor_sync(0xffffffffu, p1, 1);
            p1 += __shfl_xor_sync(0xffffffffu, p1, 2);
            if (lr == 0) {
                sRed[ng * 208 + t * 16 + lq]     = p0;
                sRed[ng * 208 + t * 16 + lq + 8] = p1;
            }
        }
    }
    __syncthreads();                             // (2)
    if (tid < T_SZ)
        out[(size_t)b * T_SZ + tid] = sRed[tid] + sRed[208 + tid] + b1v;
}

extern "C" void kernel_launch(void* const* d_in, const int* in_sizes, int n_in,
                              void* d_out, int out_size) {
    const float* query = (const float*)d_in[0];
    const float* keys  = (const float*)d_in[1];
    const float* W0    = (const float*)d_in[2];
    const float* b0    = (const float*)d_in[3];
    const float* W1    = (const float*)d_in[4];
    const float* b1    = (const float*)d_in[5];
    float* out = (float*)d_out;

    cudaFuncSetAttribute(prep, cudaFuncAttributeMaxDynamicSharedMemorySize, 102912);
    cudaFuncSetAttribute(lau_main, cudaFuncAttributeMaxDynamicSharedMemorySize, SMEM_BYTES);

    prep<<<64, 256, 102912>>>(W0, query, b0);
    lau_main<<<B_SZ, NTHR, SMEM_BYTES>>>(keys, W1, b1, out);
}